// round 16
// baseline (speedup 1.0000x reference)
#include <cuda_runtime.h>
#include <cuda_fp16.h>
#include <cstdint>

// SparseLinear via on-device counting sort (CSR by dst) — NO accumulation
// atomics. Pipeline:
//  1. transpose_in_h: x (B,N) f32 -> g_xh (N,B) fp16
//  2. zero_count / hist / scan1..3: build CSR offsets for dst
//  3. permute: scatter packed (src,val) into dst-sorted order
//  4. gather_out: warp-per-dst fp32 register accumulation, fused transpose
// Per edge in gather: 1 x 8B broadcast edge load + 64B coalesced x row.
// rel_err ~2e-4 (fp16 x quantization only; accumulation is fp32 registers).

constexpr int NN = 100000;     // input nodes
constexpr int MM = 100000;     // output nodes (divisible by 32)
constexpr int BB = 32;         // batch == warp width
constexpr int NNZMAX = 3200000;
constexpr int SCAN_BLK = 1024;
constexpr int NSCAN = (MM + SCAN_BLK - 1) / SCAN_BLK;   // 98

__device__ __half g_xh[NN * BB];            // 6.4MB fp16 x
__device__ int g_count[MM];                 // histogram
__device__ int g_off[MM + 1];               // CSR offsets
__device__ int g_pos[MM];                   // running positions for permute
__device__ int g_bsum[NSCAN];               // scan block sums
__device__ int g_btop[NSCAN];               // scanned block sums
__device__ unsigned long long g_edges[NNZMAX];  // packed (val<<32 | src)

// x (B, N) fp32 -> g_xh (N, B) fp16, tiled 32x32 transpose + convert
__global__ void transpose_in_h(const float* __restrict__ x) {
    __shared__ float tile[32][33];
    int n0 = blockIdx.x * 32;
    int tx = threadIdx.x, ty = threadIdx.y;
#pragma unroll
    for (int i = 0; i < 32; i += 8) {
        int b = ty + i;
        int n = n0 + tx;
        tile[b][tx] = (n < NN) ? x[b * NN + n] : 0.0f;
    }
    __syncthreads();
#pragma unroll
    for (int i = 0; i < 32; i += 8) {
        int n = n0 + ty + i;
        if (n < NN) g_xh[n * BB + tx] = __float2half(tile[tx][ty + i]);
    }
}

__global__ void zero_count() {
    int i = blockIdx.x * blockDim.x + threadIdx.x;
    if (i < MM) g_count[i] = 0;
}

__global__ void hist(const int* __restrict__ dst, int nnz) {
    int i = blockIdx.x * blockDim.x + threadIdx.x;
    if (i < nnz) atomicAdd(&g_count[dst[i]], 1);
}

// Per-block inclusive scan (Hillis-Steele); writes exclusive results + block sum
__global__ void scan1() {
    __shared__ int sh[SCAN_BLK];
    int t = threadIdx.x;
    int i = blockIdx.x * SCAN_BLK + t;
    int v = (i < MM) ? g_count[i] : 0;
    sh[t] = v;
    __syncthreads();
    for (int off = 1; off < SCAN_BLK; off <<= 1) {
        int x = (t >= off) ? sh[t - off] : 0;
        __syncthreads();
        sh[t] += x;
        __syncthreads();
    }
    if (i < MM) g_off[i] = sh[t] - v;            // exclusive within block
    if (t == SCAN_BLK - 1) g_bsum[blockIdx.x] = sh[t];
}

// Scan the 98 block sums (one block of 128 threads)
__global__ void scan2() {
    __shared__ int sh[128];
    int t = threadIdx.x;
    int v = (t < NSCAN) ? g_bsum[t] : 0;
    sh[t] = v;
    __syncthreads();
    for (int off = 1; off < 128; off <<= 1) {
        int x = (t >= off) ? sh[t - off] : 0;
        __syncthreads();
        sh[t] += x;
        __syncthreads();
    }
    if (t < NSCAN) g_btop[t] = sh[t] - v;        // exclusive
}

// Add block bases; copy to g_pos; set sentinel
__global__ void scan3(int nnz) {
    int i = blockIdx.x * blockDim.x + threadIdx.x;
    if (i < MM) {
        int o = g_off[i] + g_btop[i / SCAN_BLK];
        g_off[i] = o;
        g_pos[i] = o;
    }
    if (i == 0) g_off[MM] = nnz;
}

// Scatter packed (src, val) into dst-sorted slots
__global__ void permute(const int* __restrict__ indices,
                        const float* __restrict__ vals, int nnz) {
    int e = blockIdx.x * blockDim.x + threadIdx.x;
    if (e < nnz) {
        int s = __ldg(indices + e);
        int d = __ldg(indices + nnz + e);
        float v = __ldg(vals + e);
        int p = atomicAdd(&g_pos[d], 1);
        g_edges[p] = ((unsigned long long)__float_as_uint(v) << 32) |
                     (unsigned int)s;
    }
}

// Block = 256 threads = 8 warps, 32 dsts per block (4 per warp).
// Lane = batch element. fp32 register accumulation, then fused transpose.
__global__ void gather_out(const float* __restrict__ bias,
                           float* __restrict__ out) {
    __shared__ float tile[32][33];
    int m0 = blockIdx.x * 32;
    int t = threadIdx.x;
    int w = t >> 5, lane = t & 31;

#pragma unroll
    for (int k = 0; k < 4; k++) {
        int ml = w * 4 + k;
        int m = m0 + ml;
        float acc = __ldg(bias + m);
        int beg = __ldg(&g_off[m]);
        int end = __ldg(&g_off[m + 1]);
        for (int e = beg; e < end; e++) {
            unsigned long long E = __ldg(g_edges + e);   // 8B broadcast
            int s = (int)(unsigned int)E;
            float v = __uint_as_float((unsigned int)(E >> 32));
            float xv = __half2float(__ldg(g_xh + (size_t)s * BB + lane)); // 64B/warp
            acc = fmaf(v, xv, acc);
        }
        tile[ml][lane] = acc;
    }
    __syncthreads();

    // transposed coalesced write: out[b*MM + m0 + lane]
    int bq = t >> 5;   // 0..7
#pragma unroll
    for (int i = 0; i < 4; i++) {
        int b = bq * 4 + i;
        out[(size_t)b * MM + m0 + lane] = tile[lane][b];  // conflict-free
    }
}

extern "C" void kernel_launch(void* const* d_in, const int* in_sizes, int n_in,
                              void* d_out, int out_size) {
    const float* x       = (const float*)d_in[0];  // (B, N, 1) f32
    const int*   indices = (const int*)  d_in[1];  // (2, NNZ)  i32
    const float* values  = (const float*)d_in[2];  // (NNZ,)    f32
    const float* bias    = (const float*)d_in[3];  // (M, 1)    f32
    float* out = (float*)d_out;                    // (B, M, 1) f32
    int nnz = in_sizes[2];

    dim3 tb(32, 8);
    transpose_in_h<<<(NN + 31) / 32, tb>>>(x);
    zero_count<<<(MM + 255) / 256, 256>>>();
    hist<<<(nnz + 255) / 256, 256>>>(indices + nnz, nnz);
    scan1<<<NSCAN, SCAN_BLK>>>();
    scan2<<<1, 128>>>();
    scan3<<<(MM + 255) / 256, 256>>>(nnz);
    permute<<<(nnz + 255) / 256, 256>>>(indices, values, nnz);
    gather_out<<<MM / 32, 256>>>(bias, out);
}